// round 16
// baseline (speedup 1.0000x reference)
#include <cuda_runtime.h>
#include <cuda_fp16.h>
#include <cstdint>

#define TOK   2048
#define DIMSZ 1024
#define HID   2048
#define NE    8
#define NSLOT (2 * TOK)

// Scratch (allocation-free: __device__ globals)
__device__ float g_w[NSLOT];
__device__ int   g_cnt[NE];
__device__ int   g_list[NE * TOK];
__device__ int   g_done1[NE * 16];    // GEMM1 completion: (e, mblock) -> n-planes done
__device__ int   g_wpdone;            // Wp cvt CTAs done
__device__ __align__(128) __half g_xh[TOK * DIMSZ];
__device__ __align__(128) __half g_wfch[NE * HID * DIMSZ];
__device__ __align__(128) __half g_wph[NE * DIMSZ * HID];
__device__ __align__(128) __half g_h2h[NSLOT * HID];

// ---------------------------------------------------------------------------
// Helpers
// ---------------------------------------------------------------------------
__device__ __forceinline__ uint32_t smem_u32(const void* p) {
    uint32_t a;
    asm("{ .reg .u64 t; cvta.to.shared.u64 t, %1; cvt.u32.u64 %0, t; }" : "=r"(a) : "l"(p));
    return a;
}
__device__ __forceinline__ void ldm4(uint32_t* r, uint32_t addr) {
    asm volatile("ldmatrix.sync.aligned.m8n8.x4.shared.b16 {%0,%1,%2,%3}, [%4];"
        : "=r"(r[0]), "=r"(r[1]), "=r"(r[2]), "=r"(r[3]) : "r"(addr));
}
__device__ __forceinline__ void mmaf16(float* c, const uint32_t* a, const uint32_t* b) {
    asm volatile(
        "mma.sync.aligned.m16n8k16.row.col.f32.f16.f16.f32 "
        "{%0,%1,%2,%3}, {%4,%5,%6,%7}, {%8,%9}, {%0,%1,%2,%3};"
        : "+f"(c[0]), "+f"(c[1]), "+f"(c[2]), "+f"(c[3])
        : "r"(a[0]), "r"(a[1]), "r"(a[2]), "r"(a[3]), "r"(b[0]), "r"(b[1]));
}
__device__ __forceinline__ void cp16(uint32_t dst, const void* src) {
    asm volatile("cp.async.cg.shared.global [%0], [%1], 16;" :: "r"(dst), "l"(src) : "memory");
}
__device__ __forceinline__ void cp_commit() {
    asm volatile("cp.async.commit_group;" ::: "memory");
}
template<int N> __device__ __forceinline__ void cp_wait() {
    asm volatile("cp.async.wait_group %0;" :: "n"(N) : "memory");
}
// (row, 16B-chunk c in 0..3) -> swizzled byte offset within one 128x64B mat
__device__ __forceinline__ uint32_t swzoff(uint32_t row, uint32_t c) {
    uint32_t q = (((row & 1u) << 2) | c) ^ ((row >> 1) & 7u);
    return ((row >> 1) << 7) + (q << 4);
}

#define NX4 (TOK * DIMSZ / 4)
#define NF4 (NE * HID * DIMSZ / 4)     // 4194304
#define NB_CVT (NF4 / 256)             // 16384 blocks
#define NB_RTR (TOK / 8)               // 256 blocks

// ---------------------------------------------------------------------------
__global__ void k_zero_counts() {
    if (threadIdx.x < NE) g_cnt[threadIdx.x] = 0;
    if (threadIdx.x < NE * 16) g_done1[threadIdx.x] = 0;
    if (threadIdx.x == 255) g_wpdone = 0;
}

// Fused front: [0,NB_CVT) cvt Wfc->fp16 | [NB_CVT,+NB_RTR) router+x cvt |
// rest: zero out. All three are mutually independent.
__global__ void k_front(const float* __restrict__ x, const float* __restrict__ Wr,
                        const float4* __restrict__ wfc,
                        float* __restrict__ out, int out_size) {
    int b = blockIdx.x;
    if (b < NB_CVT) {
        int i = b * 256 + threadIdx.x;
        float4 v = wfc[i];
        __half2 h0 = __floats2half2_rn(v.x, v.y);
        __half2 h1 = __floats2half2_rn(v.z, v.w);
        ((uint2*)g_wfch)[i] = make_uint2(*(uint32_t*)&h0, *(uint32_t*)&h1);
        return;
    }
    if (b >= NB_CVT + NB_RTR) {
        int i = (b - NB_CVT - NB_RTR) * 256 + threadIdx.x;
        int n4 = out_size >> 2;
        if (i < n4) ((float4*)out)[i] = make_float4(0.f, 0.f, 0.f, 0.f);
        if (i == 0) {
            for (int j = n4 << 2; j < out_size; ++j) out[j] = 0.f;
        }
        return;
    }
    // Router: one warp per token; also converts this token's x row to fp16.
    int warp = threadIdx.x >> 5;
    int lane = threadIdx.x & 31;
    int t = (b - NB_CVT) * 8 + warp;

    float acc[NE];
#pragma unroll
    for (int e = 0; e < NE; ++e) acc[e] = 0.f;

    const float* xr = x + (size_t)t * DIMSZ;
    for (int i = lane; i < DIMSZ; i += 32) {
        float xv = xr[i];
#pragma unroll
        for (int e = 0; e < NE; ++e) acc[e] = fmaf(xv, Wr[e * DIMSZ + i], acc[e]);
    }
    {
        uint32_t* dst = (uint32_t*)(g_xh + (size_t)t * DIMSZ);
        const float2* src = (const float2*)xr;
#pragma unroll
        for (int i = lane; i < DIMSZ / 2; i += 32) {
            float2 v = src[i];
            __half2 h = __floats2half2_rn(v.x, v.y);
            dst[i] = *(uint32_t*)&h;
        }
    }
#pragma unroll
    for (int e = 0; e < NE; ++e) {
#pragma unroll
        for (int o = 16; o > 0; o >>= 1)
            acc[e] += __shfl_xor_sync(0xffffffffu, acc[e], o);
    }
    if (lane == 0) {
        float m = acc[0];
#pragma unroll
        for (int e = 1; e < NE; ++e) m = fmaxf(m, acc[e]);
        float p[NE]; float Z = 0.f;
#pragma unroll
        for (int e = 0; e < NE; ++e) { p[e] = expf(acc[e] - m); Z += p[e]; }
        float invZ = 1.f / Z;
#pragma unroll
        for (int e = 0; e < NE; ++e) p[e] *= invZ;

        int e0 = 0;
#pragma unroll
        for (int e = 1; e < NE; ++e) if (p[e] > p[e0]) e0 = e;
        int e1 = (e0 == 0) ? 1 : 0;
#pragma unroll
        for (int e = 0; e < NE; ++e) { if (e != e0 && p[e] > p[e1]) e1 = e; }

        float s = p[e0] + p[e1] + 1e-8f;
        g_w[2 * t]     = p[e0] / s;
        g_w[2 * t + 1] = p[e1] / s;
        int q0 = atomicAdd(&g_cnt[e0], 1); g_list[e0 * TOK + q0] = 2 * t;
        int q1 = atomicAdd(&g_cnt[e1], 1); g_list[e1 * TOK + q1] = 2 * t + 1;
    }
}

// ---------------------------------------------------------------------------
// R11 GEMM core (frozen): mma.sync m16n8k16 fp16 single-pass, fp32 accum.
// CTA = 128 threads (4 warps 2x2), tile 128x128, warp tile 64x64.
// K-slab = 32 fp16 (64B rows, XOR swizzle), 3-stage cp.async, 1 sync/slab.
#define MAT      8192
#define STG      (2 * MAT)            // 16384
#define SLOT_OFF (3 * STG)            // 49152
#define AOFF_OFF (SLOT_OFF + 512)
#define GSMEM    (AOFF_OFF + 512)

template<int KDIM, int NDIM, bool RELU2, int SHIFT>
__device__ __forceinline__ void gemm_core(const __half* __restrict__ Ahp,
                                          const __half* __restrict__ B,
                                          const int* __restrict__ list,
                                          int cnt, int m0, int n0,
                                          float* __restrict__ out) {
    constexpr int NSLAB = KDIM / 32;
    extern __shared__ char smem[];
    uint32_t sb = smem_u32(smem);
    int* s_slot = (int*)(smem + SLOT_OFF);
    int* s_aoff = (int*)(smem + AOFF_OFF);
    int tid = threadIdx.x, w = tid >> 5, lane = tid & 31;

    {
        int idx = m0 + tid;
        int sl  = list[(idx < cnt) ? idx : m0];
        s_slot[tid] = (idx < cnt) ? sl : -1;
        s_aoff[tid] = (sl >> SHIFT) * KDIM;
    }
    __syncthreads();

    int lrow = lane & 7, lchunk = lane >> 3;
    int raoff[4];
    size_t boff[4];
#pragma unroll
    for (int j = 0; j < 4; ++j) {
        int row = (4 * j + w) * 8 + lrow;
        raoff[j] = s_aoff[row] + lchunk * 8;
        boff[j]  = (size_t)(n0 + row) * KDIM + lchunk * 8;
    }

    auto issue = [&](int ks, int stage) {
        int k0 = ks * 32;
        uint32_t stg = sb + (uint32_t)stage * STG;
#pragma unroll
        for (int j = 0; j < 4; ++j) {
            uint32_t row = (uint32_t)(4 * j + w) * 8 + lrow;
            uint32_t so = stg + swzoff(row, lchunk);
            cp16(so,       Ahp + raoff[j] + k0);
            cp16(so + MAT, B + boff[j] + k0);
        }
        cp_commit();
    };

    int wy = w >> 1, wx = w & 1;
    uint32_t aQ = (((lane & 1u) << 2) | (uint32_t)(lane >> 4)) ^ (((uint32_t)(lane & 15) >> 1) & 7u);
    uint32_t aB0 = sb + (uint32_t)((wy * 64 + (lane & 15)) >> 1) * 128 + aQ * 16;
    uint32_t brow = (uint32_t)(wx * 64 + ((lane >> 4) & 1) * 8 + (lane & 7));
    uint32_t bc   = (uint32_t)((lane >> 3) & 1);
    uint32_t bQ   = (((brow & 1u) << 2) | bc) ^ ((brow >> 1) & 7u);
    uint32_t bB0  = sb + MAT + (brow >> 1) * 128 + bQ * 16;

    float acc[4][8][4];
#pragma unroll
    for (int i = 0; i < 4; ++i)
#pragma unroll
        for (int j = 0; j < 8; ++j)
#pragma unroll
            for (int r = 0; r < 4; ++r) acc[i][j][r] = 0.f;

    issue(0, 0);
    issue(1, 1);
    cp_wait<1>();
    __syncthreads();

#pragma unroll 1
    for (int ks = 0; ks < NSLAB; ++ks) {
        int cur = ks % 3;
        if (ks + 2 < NSLAB) issue(ks + 2, (ks + 2) % 3);
        else                cp_commit();

        uint32_t aS = aB0 + (uint32_t)cur * STG;
        uint32_t bS = bB0 + (uint32_t)cur * STG;
#pragma unroll
        for (int kk = 0; kk < 2; ++kk) {
            uint32_t ah[4][4], bb[4][4];
#pragma unroll
            for (int mt = 0; mt < 4; ++mt)
                ldm4(ah[mt], (aS + mt * 1024) ^ (kk * 0x20));
#pragma unroll
            for (int p = 0; p < 4; ++p)
                ldm4(bb[p], (bS + p * 1024) ^ (kk * 0x20));
#pragma unroll
            for (int mt = 0; mt < 4; ++mt)
#pragma unroll
                for (int nt = 0; nt < 8; ++nt)
                    mmaf16(acc[mt][nt], ah[mt], &bb[nt >> 1][(nt & 1) * 2]);
        }
        cp_wait<1>();
        __syncthreads();
    }

    // Epilogue
    int rbase = wy * 64 + (lane >> 2);
    int cbase = n0 + wx * 64 + (lane & 3) * 2;
#pragma unroll
    for (int mt = 0; mt < 4; ++mt) {
#pragma unroll
        for (int half = 0; half < 2; ++half) {
            int sl = s_slot[rbase + mt * 16 + half * 8];
            if (sl < 0) continue;
            if (RELU2) {
                uint32_t* oh = (uint32_t*)(g_h2h + (size_t)sl * NDIM + cbase);
#pragma unroll
                for (int nt = 0; nt < 8; ++nt) {
                    float v0 = acc[mt][nt][half * 2 + 0];
                    float v1 = acc[mt][nt][half * 2 + 1];
                    v0 = fmaxf(v0, 0.f); v0 *= v0;
                    v1 = fmaxf(v1, 0.f); v1 *= v1;
                    __half2 hp = __floats2half2_rn(v0, v1);
                    oh[nt * 4] = *(uint32_t*)&hp;
                }
            } else {
                float wgt = g_w[sl];
                float* orow = out + (size_t)(sl >> 1) * DIMSZ + cbase;
#pragma unroll
                for (int nt = 0; nt < 8; ++nt) {
                    atomicAdd(&orow[nt * 8],     wgt * acc[mt][nt][half * 2 + 0]);
                    atomicAdd(&orow[nt * 8 + 1], wgt * acc[mt][nt][half * 2 + 1]);
                }
            }
        }
    }
}

// ---------------------------------------------------------------------------
// Fused GEMM1 + WpCvt + GEMM2, one launch. Grid (16,16,13):
//   z in [0,8):  GEMM1 expert z, n0 = x*128, m0 = y*128 -> signals g_done1
//   z == 8:      Wp fp32->fp16 plane -> signals g_wpdone
//   z in [9,13): GEMM2: e = (z-9)*2 + (x>>3), n0 = (x&7)*128, m0 = y*128;
//                spins on g_done1[e][y] == 16 and g_wpdone == 256.
__global__ void __launch_bounds__(128, 2)
k_gemm_fused(const float4* __restrict__ wp_src, float* __restrict__ out) {
    int z = blockIdx.z;
    int tid = threadIdx.x;

    if (z == NE) {  // Wp conversion plane
        int flat = (blockIdx.y * 16 + blockIdx.x) * 128 + tid;
#pragma unroll 4
        for (int j = 0; j < NF4 / 32768; ++j) {
            int i = flat + j * 32768;
            float4 v = wp_src[i];
            __half2 h0 = __floats2half2_rn(v.x, v.y);
            __half2 h1 = __floats2half2_rn(v.z, v.w);
            ((uint2*)g_wph)[i] = make_uint2(*(uint32_t*)&h0, *(uint32_t*)&h1);
        }
        __syncthreads();
        if (tid == 0) { __threadfence(); atomicAdd(&g_wpdone, 1); }
        return;
    }

    if (z < NE) {   // GEMM1
        int e = z, cnt = g_cnt[e];
        int m0 = blockIdx.y * 128;
        if (m0 >= cnt) {
            if (tid == 0) atomicAdd(&g_done1[e * 16 + blockIdx.y], 1);
            return;
        }
        int n0 = blockIdx.x * 128;
        gemm_core<DIMSZ, HID, true, 1>(g_xh, g_wfch + (size_t)e * HID * DIMSZ,
                                       g_list + e * TOK, cnt, m0, n0, nullptr);
        __syncthreads();
        if (tid == 0) { __threadfence(); atomicAdd(&g_done1[e * 16 + blockIdx.y], 1); }
        return;
    }

    // GEMM2
    {
        int e  = (z - NE - 1) * 2 + (blockIdx.x >> 3);
        int n0 = (blockIdx.x & 7) * 128;
        int m0 = blockIdx.y * 128;
        int cnt = g_cnt[e];
        if (m0 >= cnt) return;
        if (tid == 0) {
            while (atomicAdd(&g_done1[e * 16 + blockIdx.y], 0) < 16 ||
                   atomicAdd(&g_wpdone, 0) < 256)
                __nanosleep(128);
            __threadfence();
        }
        __syncthreads();
        gemm_core<HID, DIMSZ, false, 0>(g_h2h, g_wph + (size_t)e * DIMSZ * HID,
                                        g_list + e * TOK, cnt, m0, n0, out);
    }
}

// ---------------------------------------------------------------------------
extern "C" void kernel_launch(void* const* d_in, const int* in_sizes, int n_in,
                              void* d_out, int out_size) {
    const float* x   = (const float*)d_in[0];   // [1, 2048, 1024]
    const float* Wr  = (const float*)d_in[1];   // [8, 1024]
    const float* Wfc = (const float*)d_in[2];   // [8, 2048, 1024]
    const float* Wp  = (const float*)d_in[3];   // [8, 1024, 2048]
    float* out = (float*)d_out;

    cudaFuncSetAttribute(k_gemm_fused,
                         cudaFuncAttributeMaxDynamicSharedMemorySize, GSMEM);

    int nb_zero = (out_size / 4 + 255) / 256 + 1;
    k_zero_counts<<<1, 256>>>();
    k_front<<<NB_CVT + NB_RTR + nb_zero, 256>>>(x, Wr, (const float4*)Wfc, out, out_size);
    k_gemm_fused<<<dim3(16, 16, NE + 1 + 4), 128, GSMEM>>>((const float4*)Wp, out);
}